// round 2
// baseline (speedup 1.0000x reference)
#include <cuda_runtime.h>

#define N_NODES   50000
#define N_EDGES   600000
#define N_GRAPHS  256

// ---------------- scratch (device globals; no allocation allowed) ----------
__device__ int   g_stride;                  // 1 = int32 indices, 2 = int64 (read low word)
__device__ float g_deg [N_NODES];
__device__ float g_dinv[N_NODES];
__device__ float g_s   [N_NODES];           // layer-1 scalar aggregate
__device__ float g_h1  [N_NODES * 64];      // relu(layer1)
__device__ float g_t1  [N_NODES * 128];     // h1 @ W2
__device__ float g_a2  [N_NODES * 128];     // aggregated layer2 (pre bias/relu)
__device__ float g_h2  [N_NODES * 128];
__device__ float g_t2  [N_NODES * 64];      // h2 @ W3
__device__ float g_a3  [N_NODES * 64];
__device__ float g_h3  [N_NODES * 64];
__device__ float g_pool[N_GRAPHS * 64];
__device__ float g_cnt [N_GRAPHS];

// ---------------- dtype detection for index buffers ----------------
// edge_index values are random in [0, 50000). If stored as little-endian
// int64, every odd 32-bit word is 0. If int32, odd words are random edge ids
// (nonzero with probability ~1). Reads only the first 8KB: in-bounds for
// both layouts.
__global__ void k_detect(const unsigned int* __restrict__ ew) {
    if (threadIdx.x == 0 && blockIdx.x == 0) {
        int s = 2;
        for (int i = 1; i < 2048; i += 2) {
            if (ew[i] != 0u) { s = 1; break; }
        }
        g_stride = s;
    }
}

__device__ __forceinline__ int load_idx(const unsigned int* __restrict__ w, int elem) {
    return (int)w[(long long)elem * g_stride];
}

// ---------------- degree / normalization ----------------
__global__ void k_init_deg() {
    int i = blockIdx.x * blockDim.x + threadIdx.x;
    if (i < N_NODES) g_deg[i] = 1.0f;   // self loop
}

__global__ void k_deg(const unsigned int* __restrict__ ei) {
    int e = blockIdx.x * blockDim.x + threadIdx.x;
    if (e < N_EDGES) {
        int d = load_idx(ei, N_EDGES + e);
        atomicAdd(&g_deg[d], 1.0f);
    }
}

__global__ void k_dinv() {
    int i = blockIdx.x * blockDim.x + threadIdx.x;
    if (i < N_NODES) g_dinv[i] = rsqrtf(g_deg[i]);
}

// ---------------- layer 1 (scalar aggregation trick) ----------------
// Layer-1 input is [N,1]; A_norm @ (x*W1) == (A_norm @ x) * W1, so aggregate
// scalars (600k scalar atomics) instead of 64-wide rows.
__global__ void k_s_self(const float* __restrict__ x) {
    int i = blockIdx.x * blockDim.x + threadIdx.x;
    if (i < N_NODES) {
        float d = g_dinv[i];
        g_s[i] = x[i] * d * d;
    }
}

__global__ void k_s_edge(const float* __restrict__ x, const unsigned int* __restrict__ ei) {
    int e = blockIdx.x * blockDim.x + threadIdx.x;
    if (e < N_EDGES) {
        int s = load_idx(ei, e);
        int d = load_idx(ei, N_EDGES + e);
        atomicAdd(&g_s[d], x[s] * g_dinv[s] * g_dinv[d]);
    }
}

__global__ void k_h1(const float* __restrict__ W1, const float* __restrict__ b1) {
    int idx = blockIdx.x * blockDim.x + threadIdx.x;
    if (idx < N_NODES * 64) {
        int n = idx >> 6, c = idx & 63;
        g_h1[idx] = fmaxf(fmaf(g_s[n], W1[c], b1[c]), 0.0f);
    }
}

// ---------------- layer 2 GEMM: t1 = h1 @ W2, a2 = self-loop term ----------
__global__ void k_gemm2(const float* __restrict__ W2) {
    __shared__ float row[64];
    int n = blockIdx.x;
    if (threadIdx.x < 64) row[threadIdx.x] = g_h1[n * 64 + threadIdx.x];
    __syncthreads();
    int c = threadIdx.x;   // 128 threads
    float acc = 0.0f;
#pragma unroll
    for (int k = 0; k < 64; k++) acc = fmaf(row[k], W2[k * 128 + c], acc);
    g_t1[n * 128 + c] = acc;
    float di = g_dinv[n];
    g_a2[n * 128 + c] = acc * di * di;
}

__global__ void k_edge_agg2(const unsigned int* __restrict__ ei) {
    int e = blockIdx.x;        // one block per edge, 128 threads
    int c = threadIdx.x;
    int s = load_idx(ei, e);
    int d = load_idx(ei, N_EDGES + e);
    float w = g_dinv[s] * g_dinv[d];
    atomicAdd(&g_a2[d * 128 + c], g_t1[s * 128 + c] * w);
}

__global__ void k_relu_bias2(const float* __restrict__ b2) {
    int idx = blockIdx.x * blockDim.x + threadIdx.x;
    if (idx < N_NODES * 128) {
        int c = idx & 127;
        g_h2[idx] = fmaxf(g_a2[idx] + b2[c], 0.0f);
    }
}

// ---------------- layer 3 GEMM: t2 = h2 @ W3 ----------------
__global__ void k_gemm3(const float* __restrict__ W3) {
    __shared__ float row[128];
    int n = blockIdx.x;
    row[threadIdx.x]      = g_h2[n * 128 + threadIdx.x];
    row[threadIdx.x + 64] = g_h2[n * 128 + threadIdx.x + 64];
    __syncthreads();
    int c = threadIdx.x;   // 64 threads
    float acc = 0.0f;
#pragma unroll
    for (int k = 0; k < 128; k++) acc = fmaf(row[k], W3[k * 64 + c], acc);
    g_t2[n * 64 + c] = acc;
    float di = g_dinv[n];
    g_a3[n * 64 + c] = acc * di * di;
}

__global__ void k_edge_agg3(const unsigned int* __restrict__ ei) {
    int e = blockIdx.x;        // one block per edge, 64 threads
    int c = threadIdx.x;
    int s = load_idx(ei, e);
    int d = load_idx(ei, N_EDGES + e);
    float w = g_dinv[s] * g_dinv[d];
    atomicAdd(&g_a3[d * 64 + c], g_t2[s * 64 + c] * w);
}

__global__ void k_relu_bias3(const float* __restrict__ b3) {
    int idx = blockIdx.x * blockDim.x + threadIdx.x;
    if (idx < N_NODES * 64) {
        int c = idx & 63;
        g_h3[idx] = fmaxf(g_a3[idx] + b3[c], 0.0f);
    }
}

// ---------------- pooling + head ----------------
__global__ void k_pool_zero() {
    int i = blockIdx.x * blockDim.x + threadIdx.x;
    if (i < N_GRAPHS * 64) g_pool[i] = 0.0f;
    if (i < N_GRAPHS) g_cnt[i] = 0.0f;
}

__global__ void k_pool(const unsigned int* __restrict__ batch) {
    int idx = blockIdx.x * blockDim.x + threadIdx.x;
    if (idx < N_NODES * 64) {
        int n = idx >> 6, c = idx & 63;
        int g = load_idx(batch, n);
        atomicAdd(&g_pool[g * 64 + c], g_h3[idx]);
        if (c == 0) atomicAdd(&g_cnt[g], 1.0f);
    }
}

__global__ void k_head(const float* __restrict__ l1w, const float* __restrict__ l1b,
                       const float* __restrict__ l2w, const float* __restrict__ l2b,
                       float* __restrict__ out) {
    int g = blockIdx.x * blockDim.x + threadIdx.x;
    if (g >= N_GRAPHS) return;
    float inv = 1.0f / fmaxf(g_cnt[g], 1.0f);
    float p[64];
#pragma unroll
    for (int k = 0; k < 64; k++) p[k] = g_pool[g * 64 + k] * inv;
    float o = l2b[0];
#pragma unroll 4
    for (int j = 0; j < 32; j++) {
        float z = l1b[j];
#pragma unroll
        for (int k = 0; k < 64; k++) z = fmaf(p[k], l1w[k * 32 + j], z);
        o = fmaf(fmaxf(z, 0.0f), l2w[j], o);
    }
    out[g] = o;
}

// ---------------- launch ----------------
extern "C" void kernel_launch(void* const* d_in, const int* in_sizes, int n_in,
                              void* d_out, int out_size) {
    const float* x   = (const float*)d_in[0];
    const float* W1  = (const float*)d_in[1];
    const float* b1  = (const float*)d_in[2];
    const float* W2  = (const float*)d_in[3];
    const float* b2  = (const float*)d_in[4];
    const float* W3  = (const float*)d_in[5];
    const float* b3  = (const float*)d_in[6];
    const float* l1w = (const float*)d_in[7];
    const float* l1b = (const float*)d_in[8];
    const float* l2w = (const float*)d_in[9];
    const float* l2b = (const float*)d_in[10];
    const unsigned int* ei    = (const unsigned int*)d_in[11];
    const unsigned int* batch = (const unsigned int*)d_in[12];
    float* out = (float*)d_out;

    const int TB = 256;
    const int gN   = (N_NODES + TB - 1) / TB;
    const int gE   = (N_EDGES + TB - 1) / TB;
    const int gN64 = (N_NODES * 64 + TB - 1) / TB;

    // dtype detection (int32 vs int64 index buffers)
    k_detect<<<1, 32>>>(ei);

    // degree / norm
    k_init_deg<<<gN, TB>>>();
    k_deg<<<gE, TB>>>(ei);
    k_dinv<<<gN, TB>>>();

    // layer 1 (scalar aggregation, then outer-product with W1)
    k_s_self<<<gN, TB>>>(x);
    k_s_edge<<<gE, TB>>>(x, ei);
    k_h1<<<gN64, TB>>>(W1, b1);

    // layer 2
    k_gemm2<<<N_NODES, 128>>>(W2);
    k_edge_agg2<<<N_EDGES, 128>>>(ei);
    k_relu_bias2<<<(N_NODES * 128 + TB - 1) / TB, TB>>>(b2);

    // layer 3
    k_gemm3<<<N_NODES, 64>>>(W3);
    k_edge_agg3<<<N_EDGES, 64>>>(ei);
    k_relu_bias3<<<gN64, TB>>>(b3);

    // pool + head
    k_pool_zero<<<(N_GRAPHS * 64 + TB - 1) / TB, TB>>>();
    k_pool<<<gN64, TB>>>(batch);
    k_head<<<1, N_GRAPHS>>>(l1w, l1b, l2w, l2b, out);
}

// round 3
// speedup vs baseline: 3.6749x; 3.6749x over previous
#include <cuda_runtime.h>

#define N_NODES   50000
#define N_EDGES   600000
#define N_GRAPHS  256
#define SCAN_BLK  512
#define N_SCANB   ((N_NODES + SCAN_BLK - 1) / SCAN_BLK)   // 98
#define NPB       16                                       // nodes per GEMM block

// ---------------- scratch (device globals; no allocation allowed) ----------
__device__ int   g_stride;                 // 1 = int32 indices, 2 = int64 (low word)
__device__ int   g_cnt_i [N_NODES];        // in-degree counts
__device__ int   g_rowptr[N_NODES + 1];    // CSR row pointers (by dst)
__device__ int   g_cursor[N_NODES];
__device__ int   g_bsum  [N_SCANB];
__device__ int   g_col   [N_EDGES];        // src per CSR slot
__device__ float g_w     [N_EDGES];        // dinv[s]*dinv[d] per CSR slot
__device__ float g_dinv  [N_NODES];
__device__ float g_s     [N_NODES];        // layer-1 scalar aggregate
__device__ float g_z1    [N_NODES * 64];   // aggregated h1
__device__ float g_h2    [N_NODES * 128];
__device__ float g_t2    [N_NODES * 64];   // h2 @ W3
__device__ float g_h3    [N_NODES * 64];
__device__ float g_pool  [N_GRAPHS * 64];
__device__ float g_cntf  [N_GRAPHS];

// ---------------- dtype detection (int32 vs int64 index buffers) -----------
// edge_index values are in [0, 50000). If int64 little-endian, every odd
// 32-bit word is 0; if int32 they're random node ids. Reads 8KB, in-bounds
// for both layouts.
__global__ void k_detect(const unsigned int* __restrict__ ew) {
    if (threadIdx.x == 0) {
        int s = 2;
        for (int i = 1; i < 2048; i += 2)
            if (ew[i] != 0u) { s = 1; break; }
        g_stride = s;
    }
}

__device__ __forceinline__ int load_idx(const unsigned int* __restrict__ w, int elem) {
    return (int)w[(long long)elem * g_stride];
}

// ---------------- zero counters ----------------
__global__ void k_zero() {
    int i = blockIdx.x * blockDim.x + threadIdx.x;
    if (i < N_NODES) g_cnt_i[i] = 0;
    if (i < N_GRAPHS * 64) g_pool[i] = 0.0f;
    if (i < N_GRAPHS) g_cntf[i] = 0.0f;
}

// ---------------- CSR build ----------------
__global__ void k_count(const unsigned int* __restrict__ ei) {
    int e = blockIdx.x * blockDim.x + threadIdx.x;
    if (e < N_EDGES) atomicAdd(&g_cnt_i[load_idx(ei, N_EDGES + e)], 1);
}

__global__ void k_scan1() {
    __shared__ int sh[SCAN_BLK];
    int t = threadIdx.x;
    int i = blockIdx.x * SCAN_BLK + t;
    int v = (i < N_NODES) ? g_cnt_i[i] : 0;
    sh[t] = v;
    __syncthreads();
#pragma unroll
    for (int off = 1; off < SCAN_BLK; off <<= 1) {
        int add = (t >= off) ? sh[t - off] : 0;
        __syncthreads();
        sh[t] += add;
        __syncthreads();
    }
    if (i < N_NODES) g_rowptr[i] = sh[t] - v;    // exclusive within block
    if (t == SCAN_BLK - 1) g_bsum[blockIdx.x] = sh[t];
}

__global__ void k_scan2() {
    if (threadIdx.x == 0) {
        int run = 0;
        for (int i = 0; i < N_SCANB; i++) { int v = g_bsum[i]; g_bsum[i] = run; run += v; }
    }
}

__global__ void k_scan3() {
    int i = blockIdx.x * blockDim.x + threadIdx.x;
    if (i < N_NODES) {
        int rp = g_rowptr[i] + g_bsum[i / SCAN_BLK];
        g_rowptr[i] = rp;
        g_cursor[i] = rp;
        g_dinv[i]   = rsqrtf((float)g_cnt_i[i] + 1.0f);
    }
    if (i == 0) g_rowptr[N_NODES] = N_EDGES;
}

__global__ void k_scatter(const unsigned int* __restrict__ ei) {
    int e = blockIdx.x * blockDim.x + threadIdx.x;
    if (e < N_EDGES) {
        int s = load_idx(ei, e);
        int d = load_idx(ei, N_EDGES + e);
        int pos = atomicAdd(&g_cursor[d], 1);
        g_col[pos] = s;
        g_w[pos]   = g_dinv[s] * g_dinv[d];
    }
}

// ---------------- layer 1 scalar aggregate: s = A_norm @ x ----------------
__global__ void k_s(const float* __restrict__ x) {
    int n = blockIdx.x * blockDim.x + threadIdx.x;
    if (n >= N_NODES) return;
    float di = g_dinv[n];
    float s = x[n] * di * di;
    int beg = g_rowptr[n], end = g_rowptr[n + 1];
    for (int j = beg; j < end; j++)
        s = fmaf(g_w[j], x[g_col[j]], s);
    g_s[n] = s;
}

// ---------------- layer 2: z1 = A_norm @ relu(s*W1 + b1) -------------------
// h1 rows are rank-1 in s, so recompute them in-register: gather is the
// 4-byte scalar s[src] instead of a 256B row.
__global__ void k_agg_l2(const float* __restrict__ W1, const float* __restrict__ b1) {
    int n = blockIdx.x;
    int c = threadIdx.x;          // 64 threads
    float w1c = W1[c], b1c = b1[c];
    float di = g_dinv[n];
    float acc = di * di * fmaxf(fmaf(g_s[n], w1c, b1c), 0.0f);
    int beg = g_rowptr[n], end = g_rowptr[n + 1];
    int j = beg;
    for (; j + 1 < end; j += 2) {
        float s0 = g_s[g_col[j]],  w0 = g_w[j];
        float s1 = g_s[g_col[j+1]], w1 = g_w[j+1];
        acc = fmaf(w0, fmaxf(fmaf(s0, w1c, b1c), 0.0f), acc);
        acc = fmaf(w1, fmaxf(fmaf(s1, w1c, b1c), 0.0f), acc);
    }
    if (j < end)
        acc = fmaf(g_w[j], fmaxf(fmaf(g_s[g_col[j]], w1c, b1c), 0.0f), acc);
    g_z1[n * 64 + c] = acc;
}

// ---------------- h2 = relu(z1 @ W2 + b2)  (weight cols in registers) ------
__global__ void __launch_bounds__(128) k_gemm2(const float* __restrict__ W2,
                                               const float* __restrict__ b2) {
    __shared__ float row[64];
    int c = threadIdx.x;          // 128 threads = output cols
    float wcol[64];
#pragma unroll
    for (int k = 0; k < 64; k++) wcol[k] = W2[k * 128 + c];
    float b = b2[c];
    int base = blockIdx.x * NPB;
    for (int ni = 0; ni < NPB; ni++) {
        int n = base + ni;
        if (c < 64) row[c] = g_z1[n * 64 + c];
        __syncthreads();
        float acc = 0.0f;
#pragma unroll
        for (int k = 0; k < 64; k++) acc = fmaf(row[k], wcol[k], acc);
        g_h2[n * 128 + c] = fmaxf(acc + b, 0.0f);
        __syncthreads();
    }
}

// ---------------- t2 = h2 @ W3  (split-K over 2 thread halves) -------------
__global__ void __launch_bounds__(128) k_gemm3(const float* __restrict__ W3) {
    __shared__ float row[128];
    __shared__ float partial[128];
    int t = threadIdx.x;
    int c = t & 63, half = t >> 6;
    float wcol[64];
#pragma unroll
    for (int kk = 0; kk < 64; kk++) wcol[kk] = W3[(half * 64 + kk) * 64 + c];
    int base = blockIdx.x * NPB;
    for (int ni = 0; ni < NPB; ni++) {
        int n = base + ni;
        row[t] = g_h2[n * 128 + t];
        __syncthreads();
        float acc = 0.0f;
        const float* r = row + half * 64;
#pragma unroll
        for (int kk = 0; kk < 64; kk++) acc = fmaf(r[kk], wcol[kk], acc);
        partial[t] = acc;
        __syncthreads();
        if (half == 0) g_t2[n * 64 + c] = partial[c] + partial[c + 64];
        __syncthreads();
    }
}

// ---------------- layer 3 aggregation: h3 = relu(A_norm @ t2 + b3) ---------
__global__ void k_agg_l3(const float* __restrict__ b3) {
    int n = blockIdx.x;
    int c = threadIdx.x;          // 64 threads
    float di = g_dinv[n];
    float acc = di * di * g_t2[n * 64 + c];
    int beg = g_rowptr[n], end = g_rowptr[n + 1];
    int j = beg;
    for (; j + 1 < end; j += 2) {
        int s0 = g_col[j], s1 = g_col[j + 1];
        float w0 = g_w[j], w1 = g_w[j + 1];
        float v0 = g_t2[s0 * 64 + c];
        float v1 = g_t2[s1 * 64 + c];
        acc = fmaf(w0, v0, acc);
        acc = fmaf(w1, v1, acc);
    }
    if (j < end)
        acc = fmaf(g_w[j], g_t2[g_col[j] * 64 + c], acc);
    g_h3[n * 64 + c] = fmaxf(acc + b3[c], 0.0f);
}

// ---------------- pooling + head ----------------
__global__ void k_pool(const unsigned int* __restrict__ batch) {
    int idx = blockIdx.x * blockDim.x + threadIdx.x;
    if (idx < N_NODES * 64) {
        int n = idx >> 6, c = idx & 63;
        int g = load_idx(batch, n);
        atomicAdd(&g_pool[g * 64 + c], g_h3[idx]);
        if (c == 0) atomicAdd(&g_cntf[g], 1.0f);
    }
}

__global__ void k_head(const float* __restrict__ l1w, const float* __restrict__ l1b,
                       const float* __restrict__ l2w, const float* __restrict__ l2b,
                       float* __restrict__ out) {
    int g = blockIdx.x * blockDim.x + threadIdx.x;
    if (g >= N_GRAPHS) return;
    float inv = 1.0f / fmaxf(g_cntf[g], 1.0f);
    float p[64];
#pragma unroll
    for (int k = 0; k < 64; k++) p[k] = g_pool[g * 64 + k] * inv;
    float o = l2b[0];
#pragma unroll 4
    for (int j = 0; j < 32; j++) {
        float z = l1b[j];
#pragma unroll
        for (int k = 0; k < 64; k++) z = fmaf(p[k], l1w[k * 32 + j], z);
        o = fmaf(fmaxf(z, 0.0f), l2w[j], o);
    }
    out[g] = o;
}

// ---------------- launch ----------------
extern "C" void kernel_launch(void* const* d_in, const int* in_sizes, int n_in,
                              void* d_out, int out_size) {
    const float* x   = (const float*)d_in[0];
    const float* W1  = (const float*)d_in[1];
    const float* b1  = (const float*)d_in[2];
    const float* W2  = (const float*)d_in[3];
    const float* b2  = (const float*)d_in[4];
    const float* W3  = (const float*)d_in[5];
    const float* b3  = (const float*)d_in[6];
    const float* l1w = (const float*)d_in[7];
    const float* l1b = (const float*)d_in[8];
    const float* l2w = (const float*)d_in[9];
    const float* l2b = (const float*)d_in[10];
    const unsigned int* ei    = (const unsigned int*)d_in[11];
    const unsigned int* batch = (const unsigned int*)d_in[12];
    float* out = (float*)d_out;

    const int TB = 256;
    const int gN   = (N_NODES + TB - 1) / TB;
    const int gE   = (N_EDGES + TB - 1) / TB;
    const int gN64 = (N_NODES * 64 + TB - 1) / TB;

    k_detect<<<1, 32>>>(ei);
    k_zero<<<gN, TB>>>();

    // CSR by destination
    k_count  <<<gE, TB>>>(ei);
    k_scan1  <<<N_SCANB, SCAN_BLK>>>();
    k_scan2  <<<1, 32>>>();
    k_scan3  <<<gN, TB>>>();
    k_scatter<<<gE, TB>>>(ei);

    // layer 1 scalar aggregate
    k_s<<<gN, TB>>>(x);

    // layer 2: aggregate (recomputing h1 from s) then GEMM
    k_agg_l2<<<N_NODES, 64>>>(W1, b1);
    k_gemm2 <<<N_NODES / NPB, 128>>>(W2, b2);

    // layer 3: GEMM then aggregate (+bias+relu)
    k_gemm3 <<<N_NODES / NPB, 128>>>(W3);
    k_agg_l3<<<N_NODES, 64>>>(b3);

    // pool + head
    k_pool<<<gN64, TB>>>(batch);
    k_head<<<1, N_GRAPHS>>>(l1w, l1b, l2w, l2b, out);
}